// round 4
// baseline (speedup 1.0000x reference)
#include <cuda_runtime.h>
#include <math.h>

#define N_NODES 100000
#define N_EDGES 1600000
#define D_IN    256
#define D_H     128
#define D_OUT   47

// ---------------- scratch (no allocations allowed) ----------------
__device__ float g_h1  [(size_t)N_NODES * D_H];    // layer-1 GEMM out, later reused for relu/dropout result
__device__ float g_agg1[(size_t)N_NODES * D_H];    // layer-1 aggregation
__device__ float g_h2  [(size_t)N_NODES * D_OUT];  // layer-2 GEMM out
__device__ float g_agg2[(size_t)N_NODES * D_OUT];  // layer-2 aggregation
__device__ int   g_src [N_EDGES];
__device__ int   g_dst [N_EDGES];
__device__ float g_nsrc[N_NODES];
__device__ float g_ndst[N_NODES];
__device__ int   g_degs[N_NODES];
__device__ int   g_degd[N_NODES];

// ---------------- zero pass ----------------
__global__ void zero_kernel() {
    int idx = blockIdx.x * blockDim.x + threadIdx.x;
    int stride = gridDim.x * blockDim.x;
    for (int i = idx; i < N_NODES * D_H; i += stride)  g_agg1[i] = 0.f;
    for (int i = idx; i < N_NODES * D_OUT; i += stride) g_agg2[i] = 0.f;
    for (int i = idx; i < N_NODES; i += stride) { g_degs[i] = 0; g_degd[i] = 0; }
}

// ---------------- edge index normalization (int64 vs int32 detect) ----------------
__global__ void conv_idx_kernel(const void* __restrict__ ei) {
    const int* p32 = (const int*)ei;
    // int64 little-endian with values < 1e5: every odd 32-bit word is 0.
    bool is64 = true;
#pragma unroll
    for (int i = 0; i < 16; i++) is64 = is64 && (p32[2 * i + 1] == 0);

    long long total = 2LL * N_EDGES;
    long long stride = (long long)gridDim.x * blockDim.x;
    for (long long e = blockIdx.x * (long long)blockDim.x + threadIdx.x; e < total; e += stride) {
        int v;
        if (is64) v = (int)((const long long*)ei)[e];
        else      v = p32[e];
        if (e < N_EDGES) g_src[e] = v;
        else             g_dst[e - N_EDGES] = v;
    }
}

// ---------------- degrees + norms ----------------
__global__ void degree_kernel() {
    int stride = gridDim.x * blockDim.x;
    for (int e = blockIdx.x * blockDim.x + threadIdx.x; e < N_EDGES; e += stride) {
        atomicAdd(&g_degs[g_src[e]], 1);
        atomicAdd(&g_degd[g_dst[e]], 1);
    }
}

__global__ void norm_kernel() {
    int i = blockIdx.x * blockDim.x + threadIdx.x;
    if (i < N_NODES) {
        int ds = g_degs[i]; if (ds < 1) ds = 1;
        int dd = g_degd[i]; if (dd < 1) dd = 1;
        g_nsrc[i] = 1.0f / sqrtf((float)ds);
        g_ndst[i] = 1.0f / sqrtf((float)dd);
    }
}

// ---------------- register-tiled fp32 GEMM: C = (diag(rowscale)*A) @ B ----------------
template<int BM, int BN, int BK, int TM, int TN>
__global__ void gemm_kernel(const float* __restrict__ A, const float* __restrict__ B,
                            const float* __restrict__ rowscale, float* __restrict__ C,
                            int M, int N, int K)
{
    constexpr int TX = BN / TN;
    constexpr int TY = BM / TM;
    constexpr int NT = TX * TY;

    __shared__ float As[BK][BM + 1];
    __shared__ float Bs[BK][BN + 1];

    int tid = threadIdx.x;
    int tx = tid % TX;
    int ty = tid / TX;
    int rowBase = blockIdx.x * BM;
    int colBase = blockIdx.y * BN;

    float acc[TM][TN];
#pragma unroll
    for (int i = 0; i < TM; i++)
#pragma unroll
        for (int j = 0; j < TN; j++) acc[i][j] = 0.f;

    for (int k0 = 0; k0 < K; k0 += BK) {
#pragma unroll 8
        for (int p = tid; p < BM * BK; p += NT) {
            int r = p / BK, c = p % BK;
            int gr = rowBase + r, gc = k0 + c;
            float v = 0.f;
            if (gr < M && gc < K) {
                v = A[(long long)gr * K + gc];
                if (rowscale) v *= rowscale[gr];
            }
            As[c][r] = v;
        }
#pragma unroll 8
        for (int p = tid; p < BK * BN; p += NT) {
            int r = p / BN, c = p % BN;
            int gr = k0 + r, gc = colBase + c;
            Bs[r][c] = (gr < K && gc < N) ? B[(long long)gr * N + gc] : 0.f;
        }
        __syncthreads();

#pragma unroll
        for (int kk = 0; kk < BK; kk++) {
            float a[TM], b[TN];
#pragma unroll
            for (int i = 0; i < TM; i++) a[i] = As[kk][ty * TM + i];
#pragma unroll
            for (int j = 0; j < TN; j++) b[j] = Bs[kk][tx * TN + j];
#pragma unroll
            for (int i = 0; i < TM; i++)
#pragma unroll
                for (int j = 0; j < TN; j++) acc[i][j] += a[i] * b[j];
        }
        __syncthreads();
    }

#pragma unroll
    for (int i = 0; i < TM; i++) {
        int gr = rowBase + ty * TM + i;
        if (gr >= M) continue;
#pragma unroll
        for (int j = 0; j < TN; j++) {
            int gc = colBase + tx * TN + j;
            if (gc < N) C[(long long)gr * N + gc] = acc[i][j];
        }
    }
}

// ---------------- layer-1 edge scatter: agg1[dst] += h1[src]  (128 floats / edge) ----------------
__global__ void scatter1_kernel() {
    long long items = (long long)N_EDGES * 32;   // 32 float4s per edge
    long long stride = (long long)gridDim.x * blockDim.x;
    for (long long id = blockIdx.x * (long long)blockDim.x + threadIdx.x; id < items; id += stride) {
        int e  = (int)(id >> 5);
        int f4 = (int)(id & 31);
        int s = g_src[e];
        int d = g_dst[e];
        float4 v = ((const float4*)(g_h1 + (long long)s * D_H))[f4];
        float* base = g_agg1 + (long long)d * D_H + f4 * 4;
        atomicAdd(base + 0, v.x);
        atomicAdd(base + 1, v.y);
        atomicAdd(base + 2, v.z);
        atomicAdd(base + 3, v.w);
    }
}

// ---------------- JAX threefry2x32 (key = (0, 42)) ----------------
__device__ __forceinline__ unsigned rotl32(unsigned x, int r) {
    return (x << r) | (x >> (32 - r));
}

__device__ __forceinline__ void threefry2x32_k42(unsigned x0, unsigned x1, unsigned& o0, unsigned& o1) {
    const unsigned k0 = 0u, k1 = 42u;
    const unsigned k2 = k0 ^ k1 ^ 0x1BD11BDAu;
    unsigned ks[3] = {k0, k1, k2};
    const int rotE[4] = {13, 15, 26, 6};
    const int rotO[4] = {17, 29, 16, 24};
    x0 += ks[0];
    x1 += ks[1];
#pragma unroll
    for (int i = 0; i < 5; i++) {
        const int* rot = (i & 1) ? rotO : rotE;
#pragma unroll
        for (int j = 0; j < 4; j++) {
            x0 += x1;
            x1 = rotl32(x1, rot[j]);
            x1 ^= x0;
        }
        x0 += ks[(i + 1) % 3];
        x1 += ks[(i + 2) % 3] + (unsigned)(i + 1);
    }
    o0 = x0;
    o1 = x1;
}

// scale by norm_dst, add bias, relu, dropout. agg1 -> h1 (reuse).
// PARTITIONABLE threefry (modern JAX default): per element j,
//   (y0, y1) = threefry2x32(key=(0,42), (hi32(j)=0, lo32(j)=j));  bits = y0 ^ y1
//   u = bitcast((bits >> 9) | 0x3f800000) - 1;  keep = u < 0.8
__global__ void relu_dropout_kernel(const float* __restrict__ b1) {
    int stride = gridDim.x * blockDim.x;
    for (int j = blockIdx.x * blockDim.x + threadIdx.x; j < N_NODES * D_H; j += stride) {
        unsigned y0, y1;
        threefry2x32_k42(0u, (unsigned)j, y0, y1);
        unsigned bits = y0 ^ y1;
        float u = __uint_as_float((bits >> 9) | 0x3f800000u) - 1.0f;
        int node = j >> 7, f = j & 127;
        float v = g_agg1[j] * g_ndst[node] + b1[f];
        v = fmaxf(v, 0.f);
        g_h1[j] = (u < 0.8f) ? v / 0.8f : 0.f;
    }
}

// ---------------- layer-2 edge scatter: agg2[dst] += h2[src]  (47 floats / edge, warp per edge) ----------------
__global__ void scatter2_kernel() {
    int warp_g = (blockIdx.x * blockDim.x + threadIdx.x) >> 5;
    int lane = threadIdx.x & 31;
    if (warp_g >= N_EDGES) return;
    int s = g_src[warp_g];
    int d = g_dst[warp_g];
    const float* hs = g_h2 + (long long)s * D_OUT;
    float* ad = g_agg2 + (long long)d * D_OUT;
    atomicAdd(ad + lane, hs[lane]);              // lanes 0..31 (< 47)
    int f2 = lane + 32;
    if (f2 < D_OUT) atomicAdd(ad + f2, hs[f2]);  // lanes 0..14
}

// ---------------- final: scale, bias, log_softmax (warp per node) ----------------
__global__ void logsoftmax_kernel(const float* __restrict__ b2, float* __restrict__ out) {
    int warp_g = (blockIdx.x * blockDim.x + threadIdx.x) >> 5;
    int lane = threadIdx.x & 31;
    if (warp_g >= N_NODES) return;
    float nd = g_ndst[warp_g];
    const float* a = g_agg2 + (long long)warp_g * D_OUT;

    float v1 = a[lane] * nd + b2[lane];
    int f2 = lane + 32;
    bool has2 = (f2 < D_OUT);
    float v2 = has2 ? (a[f2] * nd + b2[f2]) : __int_as_float(0xff800000);

    float m = fmaxf(v1, v2);
#pragma unroll
    for (int o = 16; o > 0; o >>= 1) m = fmaxf(m, __shfl_xor_sync(0xffffffffu, m, o));

    float s = expf(v1 - m) + (has2 ? expf(v2 - m) : 0.f);
#pragma unroll
    for (int o = 16; o > 0; o >>= 1) s += __shfl_xor_sync(0xffffffffu, s, o);

    float lse = m + logf(s);
    out[(long long)warp_g * D_OUT + lane] = v1 - lse;
    if (has2) out[(long long)warp_g * D_OUT + f2] = v2 - lse;
}

// ---------------- launch ----------------
extern "C" void kernel_launch(void* const* d_in, const int* in_sizes, int n_in,
                              void* d_out, int out_size) {
    const float* x  = (const float*)d_in[0];
    const void*  ei = d_in[1];
    const float* W1 = (const float*)d_in[2];
    const float* b1 = (const float*)d_in[3];
    const float* W2 = (const float*)d_in[4];
    const float* b2 = (const float*)d_in[5];
    float* out = (float*)d_out;

    float *p_h1, *p_h2, *p_nsrc;
    cudaGetSymbolAddress((void**)&p_h1,   g_h1);
    cudaGetSymbolAddress((void**)&p_h2,   g_h2);
    cudaGetSymbolAddress((void**)&p_nsrc, g_nsrc);

    zero_kernel<<<25000, 256>>>();
    conv_idx_kernel<<<12500, 256>>>(ei);
    degree_kernel<<<6250, 256>>>();
    norm_kernel<<<(N_NODES + 255) / 256, 256>>>();

    // h1 = (diag(nsrc)*x) @ W1   [100000,256]x[256,128]
    gemm_kernel<128, 128, 16, 8, 8>
        <<<dim3((N_NODES + 127) / 128, 1), 256>>>(x, W1, p_nsrc, p_h1, N_NODES, D_H, D_IN);

    scatter1_kernel<<<200000, 256>>>();
    relu_dropout_kernel<<<50000, 256>>>(b1);

    // h2 = (diag(nsrc)*h1) @ W2   [100000,128]x[128,47]
    gemm_kernel<128, 48, 16, 8, 8>
        <<<dim3((N_NODES + 127) / 128, 1), 96>>>(p_h1, W2, p_nsrc, p_h2, N_NODES, D_OUT, D_H);

    scatter2_kernel<<<200000, 256>>>();
    logsoftmax_kernel<<<(N_NODES * 32 + 255) / 256, 256>>>(b2, out);
}

// round 5
// speedup vs baseline: 1.8660x; 1.8660x over previous
#include <cuda_runtime.h>
#include <math.h>

#define N_NODES 100000
#define N_EDGES 1600000
#define D_IN    256
#define D_H     128
#define D_OUT   47
#define SCAN_BLOCKS ((N_NODES + 255) / 256)   // 391

// ---------------- scratch (no allocations allowed) ----------------
__device__ float g_h1  [(size_t)N_NODES * D_H];    // layer-1 GEMM out
__device__ float g_h1d [(size_t)N_NODES * D_H];    // layer-1 aggregated+relu+dropout
__device__ float g_h2  [(size_t)N_NODES * D_OUT];  // layer-2 GEMM out
__device__ int   g_src [N_EDGES];
__device__ int   g_dst [N_EDGES];
__device__ int   g_csr_src[N_EDGES];               // src ids grouped by dst
__device__ int   g_row_ptr[N_NODES + 1];
__device__ float g_nsrc[N_NODES];
__device__ float g_ndst[N_NODES];
__device__ int   g_degs[N_NODES];                  // src degree, then reused as CSR fill cursor
__device__ int   g_degd[N_NODES];
__device__ int   g_blocksum[SCAN_BLOCKS];
__device__ int   g_blockoff[SCAN_BLOCKS];

// ---------------- zero degrees ----------------
__global__ void zero_kernel() {
    int i = blockIdx.x * blockDim.x + threadIdx.x;
    if (i < N_NODES) { g_degs[i] = 0; g_degd[i] = 0; }
}

// ---------------- edge index normalization (int64 vs int32 detect) ----------------
__global__ void conv_idx_kernel(const void* __restrict__ ei) {
    const int* p32 = (const int*)ei;
    bool is64 = true;
#pragma unroll
    for (int i = 0; i < 16; i++) is64 = is64 && (p32[2 * i + 1] == 0);

    long long total = 2LL * N_EDGES;
    long long stride = (long long)gridDim.x * blockDim.x;
    for (long long e = blockIdx.x * (long long)blockDim.x + threadIdx.x; e < total; e += stride) {
        int v;
        if (is64) v = (int)((const long long*)ei)[e];
        else      v = p32[e];
        if (e < N_EDGES) g_src[e] = v;
        else             g_dst[e - N_EDGES] = v;
    }
}

// ---------------- degrees + norms ----------------
__global__ void degree_kernel() {
    int stride = gridDim.x * blockDim.x;
    for (int e = blockIdx.x * blockDim.x + threadIdx.x; e < N_EDGES; e += stride) {
        atomicAdd(&g_degs[g_src[e]], 1);
        atomicAdd(&g_degd[g_dst[e]], 1);
    }
}

__global__ void norm_kernel() {
    int i = blockIdx.x * blockDim.x + threadIdx.x;
    if (i < N_NODES) {
        int ds = g_degs[i]; if (ds < 1) ds = 1;
        int dd = g_degd[i]; if (dd < 1) dd = 1;
        g_nsrc[i] = 1.0f / sqrtf((float)ds);
        g_ndst[i] = 1.0f / sqrtf((float)dd);
        g_degs[i] = 0;                       // reuse as CSR fill cursor
    }
    if (i == 0) g_row_ptr[N_NODES] = N_EDGES;
}

// ---------------- 3-step exclusive scan of g_degd -> g_row_ptr ----------------
__global__ void scan1_kernel() {   // per-block sums
    __shared__ int sh[256];
    int i = blockIdx.x * 256 + threadIdx.x;
    int v = (i < N_NODES) ? g_degd[i] : 0;
    sh[threadIdx.x] = v;
    __syncthreads();
    for (int o = 128; o > 0; o >>= 1) {
        if (threadIdx.x < o) sh[threadIdx.x] += sh[threadIdx.x + o];
        __syncthreads();
    }
    if (threadIdx.x == 0) g_blocksum[blockIdx.x] = sh[0];
}

__global__ void scan2_kernel() {   // single-block exclusive scan of block sums
    __shared__ int buf[2][512];
    int t = threadIdx.x;
    int v = (t < SCAN_BLOCKS) ? g_blocksum[t] : 0;
    buf[0][t] = v;
    __syncthreads();
    int cur = 0;
#pragma unroll
    for (int o = 1; o < 512; o <<= 1) {
        int nxt = cur ^ 1;
        int val = buf[cur][t];
        if (t >= o) val += buf[cur][t - o];
        buf[nxt][t] = val;
        cur = nxt;
        __syncthreads();
    }
    if (t < SCAN_BLOCKS) g_blockoff[t] = buf[cur][t] - v;  // exclusive
}

__global__ void scan3_kernel() {   // per-block exclusive scan + offset
    __shared__ int buf[2][256];
    int t = threadIdx.x;
    int i = blockIdx.x * 256 + t;
    int v = (i < N_NODES) ? g_degd[i] : 0;
    buf[0][t] = v;
    __syncthreads();
    int cur = 0;
#pragma unroll
    for (int o = 1; o < 256; o <<= 1) {
        int nxt = cur ^ 1;
        int val = buf[cur][t];
        if (t >= o) val += buf[cur][t - o];
        buf[nxt][t] = val;
        cur = nxt;
        __syncthreads();
    }
    if (i < N_NODES) g_row_ptr[i] = g_blockoff[blockIdx.x] + buf[cur][t] - v;
}

// ---------------- CSR fill: group edges by dst ----------------
__global__ void csr_fill_kernel() {
    int stride = gridDim.x * blockDim.x;
    for (int e = blockIdx.x * blockDim.x + threadIdx.x; e < N_EDGES; e += stride) {
        int d = g_dst[e];
        int pos = g_row_ptr[d] + atomicAdd(&g_degs[d], 1);
        g_csr_src[pos] = g_src[e];
    }
}

// ---------------- register-tiled fp32 GEMM: C = (diag(rowscale)*A) @ B ----------------
template<int BM, int BN, int BK, int TM, int TN>
__global__ void gemm_kernel(const float* __restrict__ A, const float* __restrict__ B,
                            const float* __restrict__ rowscale, float* __restrict__ C,
                            int M, int N, int K)
{
    constexpr int TX = BN / TN;
    constexpr int TY = BM / TM;
    constexpr int NT = TX * TY;

    __shared__ float As[BK][BM + 1];
    __shared__ float Bs[BK][BN + 1];

    int tid = threadIdx.x;
    int tx = tid % TX;
    int ty = tid / TX;
    int rowBase = blockIdx.x * BM;
    int colBase = blockIdx.y * BN;

    float acc[TM][TN];
#pragma unroll
    for (int i = 0; i < TM; i++)
#pragma unroll
        for (int j = 0; j < TN; j++) acc[i][j] = 0.f;

    for (int k0 = 0; k0 < K; k0 += BK) {
#pragma unroll 8
        for (int p = tid; p < BM * BK; p += NT) {
            int r = p / BK, c = p % BK;
            int gr = rowBase + r, gc = k0 + c;
            float v = 0.f;
            if (gr < M && gc < K) {
                v = A[(long long)gr * K + gc];
                if (rowscale) v *= rowscale[gr];
            }
            As[c][r] = v;
        }
#pragma unroll 8
        for (int p = tid; p < BK * BN; p += NT) {
            int r = p / BN, c = p % BN;
            int gr = k0 + r, gc = colBase + c;
            Bs[r][c] = (gr < K && gc < N) ? B[(long long)gr * N + gc] : 0.f;
        }
        __syncthreads();

#pragma unroll
        for (int kk = 0; kk < BK; kk++) {
            float a[TM], b[TN];
#pragma unroll
            for (int i = 0; i < TM; i++) a[i] = As[kk][ty * TM + i];
#pragma unroll
            for (int j = 0; j < TN; j++) b[j] = Bs[kk][tx * TN + j];
#pragma unroll
            for (int i = 0; i < TM; i++)
#pragma unroll
                for (int j = 0; j < TN; j++) acc[i][j] += a[i] * b[j];
        }
        __syncthreads();
    }

#pragma unroll
    for (int i = 0; i < TM; i++) {
        int gr = rowBase + ty * TM + i;
        if (gr >= M) continue;
#pragma unroll
        for (int j = 0; j < TN; j++) {
            int gc = colBase + tx * TN + j;
            if (gc < N) C[(long long)gr * N + gc] = acc[i][j];
        }
    }
}

// ---------------- JAX threefry2x32 (key = (0, 42)) ----------------
__device__ __forceinline__ unsigned rotl32(unsigned x, int r) {
    return (x << r) | (x >> (32 - r));
}

__device__ __forceinline__ unsigned threefry_bits_k42(unsigned x1) {
    // partitionable path: (y0,y1) = threefry2x32((0,42),(0,x1)); return y0^y1
    const unsigned k0 = 0u, k1 = 42u;
    const unsigned k2 = k0 ^ k1 ^ 0x1BD11BDAu;
    unsigned ks[3] = {k0, k1, k2};
    const int rotE[4] = {13, 15, 26, 6};
    const int rotO[4] = {17, 29, 16, 24};
    unsigned x0 = 0u;
    x0 += ks[0];
    x1 += ks[1];
#pragma unroll
    for (int i = 0; i < 5; i++) {
        const int* rot = (i & 1) ? rotO : rotE;
#pragma unroll
        for (int j = 0; j < 4; j++) {
            x0 += x1;
            x1 = rotl32(x1, rot[j]);
            x1 ^= x0;
        }
        x0 += ks[(i + 1) % 3];
        x1 += ks[(i + 2) % 3] + (unsigned)(i + 1);
    }
    return x0 ^ x1;
}

// ---------------- gather1 + ndst + bias + relu + dropout (warp per node) ----------------
__global__ void gather1_kernel(const float* __restrict__ b1) {
    int node = (blockIdx.x * blockDim.x + threadIdx.x) >> 5;
    int lane = threadIdx.x & 31;
    if (node >= N_NODES) return;
    int beg = g_row_ptr[node], end = g_row_ptr[node + 1];

    float4 acc = make_float4(0.f, 0.f, 0.f, 0.f);
    int e = beg;
    for (; e + 1 < end; e += 2) {
        int s0 = g_csr_src[e];
        int s1 = g_csr_src[e + 1];
        float4 v0 = ((const float4*)(g_h1 + (size_t)s0 * D_H))[lane];
        float4 v1 = ((const float4*)(g_h1 + (size_t)s1 * D_H))[lane];
        acc.x += v0.x; acc.y += v0.y; acc.z += v0.z; acc.w += v0.w;
        acc.x += v1.x; acc.y += v1.y; acc.z += v1.z; acc.w += v1.w;
    }
    if (e < end) {
        int s0 = g_csr_src[e];
        float4 v0 = ((const float4*)(g_h1 + (size_t)s0 * D_H))[lane];
        acc.x += v0.x; acc.y += v0.y; acc.z += v0.z; acc.w += v0.w;
    }

    float nd = g_ndst[node];
    float4 bb = ((const float4*)b1)[lane];
    float r[4];
    r[0] = fmaxf(acc.x * nd + bb.x, 0.f);
    r[1] = fmaxf(acc.y * nd + bb.y, 0.f);
    r[2] = fmaxf(acc.z * nd + bb.z, 0.f);
    r[3] = fmaxf(acc.w * nd + bb.w, 0.f);

    unsigned jbase = ((unsigned)node << 7) + (unsigned)(lane * 4);
#pragma unroll
    for (int t = 0; t < 4; t++) {
        unsigned bits = threefry_bits_k42(jbase + t);
        float u = __uint_as_float((bits >> 9) | 0x3f800000u) - 1.0f;
        r[t] = (u < 0.8f) ? r[t] / 0.8f : 0.f;
    }
    ((float4*)(g_h1d + (size_t)node * D_H))[lane] = make_float4(r[0], r[1], r[2], r[3]);
}

// ---------------- gather2 + ndst + bias + log_softmax (warp per node) ----------------
__global__ void gather2_kernel(const float* __restrict__ b2, float* __restrict__ out) {
    int node = (blockIdx.x * blockDim.x + threadIdx.x) >> 5;
    int lane = threadIdx.x & 31;
    if (node >= N_NODES) return;
    int beg = g_row_ptr[node], end = g_row_ptr[node + 1];
    bool has2 = (lane < D_OUT - 32);   // lane+32 < 47

    float a1 = 0.f, a2 = 0.f;
    for (int e = beg; e < end; e++) {
        int s = g_csr_src[e];
        const float* hs = g_h2 + (size_t)s * D_OUT;
        a1 += hs[lane];
        if (has2) a2 += hs[lane + 32];
    }

    float nd = g_ndst[node];
    float v1 = a1 * nd + b2[lane];
    float v2 = has2 ? (a2 * nd + b2[lane + 32]) : __int_as_float(0xff800000);

    float m = fmaxf(v1, v2);
#pragma unroll
    for (int o = 16; o > 0; o >>= 1) m = fmaxf(m, __shfl_xor_sync(0xffffffffu, m, o));

    float s = expf(v1 - m) + (has2 ? expf(v2 - m) : 0.f);
#pragma unroll
    for (int o = 16; o > 0; o >>= 1) s += __shfl_xor_sync(0xffffffffu, s, o);

    float lse = m + logf(s);
    out[(size_t)node * D_OUT + lane] = v1 - lse;
    if (has2) out[(size_t)node * D_OUT + lane + 32] = v2 - lse;
}

// ---------------- launch ----------------
extern "C" void kernel_launch(void* const* d_in, const int* in_sizes, int n_in,
                              void* d_out, int out_size) {
    const float* x  = (const float*)d_in[0];
    const void*  ei = d_in[1];
    const float* W1 = (const float*)d_in[2];
    const float* b1 = (const float*)d_in[3];
    const float* W2 = (const float*)d_in[4];
    const float* b2 = (const float*)d_in[5];
    float* out = (float*)d_out;

    float *p_h1, *p_h1d, *p_h2, *p_nsrc;
    cudaGetSymbolAddress((void**)&p_h1,   g_h1);
    cudaGetSymbolAddress((void**)&p_h1d,  g_h1d);
    cudaGetSymbolAddress((void**)&p_h2,   g_h2);
    cudaGetSymbolAddress((void**)&p_nsrc, g_nsrc);

    zero_kernel<<<SCAN_BLOCKS, 256>>>();
    conv_idx_kernel<<<12500, 256>>>(ei);
    degree_kernel<<<6250, 256>>>();
    norm_kernel<<<SCAN_BLOCKS, 256>>>();

    scan1_kernel<<<SCAN_BLOCKS, 256>>>();
    scan2_kernel<<<1, 512>>>();
    scan3_kernel<<<SCAN_BLOCKS, 256>>>();
    csr_fill_kernel<<<6250, 256>>>();

    // h1 = (diag(nsrc)*x) @ W1   [100000,256]x[256,128]
    gemm_kernel<128, 128, 16, 8, 8>
        <<<dim3((N_NODES + 127) / 128, 1), 256>>>(x, W1, p_nsrc, p_h1, N_NODES, D_H, D_IN);

    // agg1 + relu + dropout fused (warp per node)
    gather1_kernel<<<(N_NODES * 32 + 255) / 256, 256>>>(b1);

    // h2 = (diag(nsrc)*h1d) @ W2   [100000,128]x[128,47]
    gemm_kernel<128, 48, 16, 8, 8>
        <<<dim3((N_NODES + 127) / 128, 1), 96>>>(p_h1d, W2, p_nsrc, p_h2, N_NODES, D_OUT, D_H);

    // agg2 + log_softmax fused (warp per node)
    gather2_kernel<<<(N_NODES * 32 + 255) / 256, 256>>>(b2, out);
}

// round 7
// speedup vs baseline: 3.6339x; 1.9475x over previous
#include <cuda_runtime.h>
#include <math.h>
#include <stdint.h>

#define N_NODES 100000
#define N_EDGES 1600000
#define D_IN    256
#define D_H     128
#define D_OUT   47
#define SCAN_BLOCKS ((N_NODES + 255) / 256)   // 391

// ---------------- scratch (no allocations allowed) ----------------
__device__ float g_h1  [(size_t)N_NODES * D_H];    // layer-1 GEMM out
__device__ float g_h1d [(size_t)N_NODES * D_H];    // layer-1 aggregated+relu+dropout
__device__ float g_h2  [(size_t)N_NODES * D_OUT];  // layer-2 GEMM out
__device__ int   g_src [N_EDGES];
__device__ int   g_dst [N_EDGES];
__device__ int   g_csr_src[N_EDGES];               // src ids grouped by dst
__device__ int   g_row_ptr[N_NODES + 1];
__device__ float g_nsrc[N_NODES];
__device__ float g_ndst[N_NODES];
__device__ int   g_degs[N_NODES];                  // src degree, then reused as CSR fill cursor
__device__ int   g_degd[N_NODES];
__device__ int   g_blocksum[SCAN_BLOCKS];
__device__ int   g_blockoff[SCAN_BLOCKS];

__device__ __forceinline__ float to_tf32(float x) {
    float r;
    asm("cvt.rna.tf32.f32 %0, %1;" : "=f"(r) : "f"(x));
    return r;
}

__device__ __forceinline__ void mma_tf32(float* c, uint32_t a0, uint32_t a1, uint32_t a2,
                                         uint32_t a3, uint32_t b0, uint32_t b1) {
    asm volatile("mma.sync.aligned.m16n8k8.row.col.f32.tf32.tf32.f32 "
                 "{%0,%1,%2,%3}, {%4,%5,%6,%7}, {%8,%9}, {%0,%1,%2,%3};"
                 : "+f"(c[0]), "+f"(c[1]), "+f"(c[2]), "+f"(c[3])
                 : "r"(a0), "r"(a1), "r"(a2), "r"(a3), "r"(b0), "r"(b1));
}

// ================= TF32 mma.sync GEMM: C = (diag(rowscale)*A) @ B =================
// CTA tile: 128 x N_TILE. 256 threads = 8 warps as 4(m) x 2(n).
// Warp tile: 32 x (N_TILE/2). K processed in phases of 64 held in SMEM (tf32).
// A smem: [128][68] (row-major, pad 4) ; B smem: [64][N_TILE+8] (k-major rows).
template<int N_TILE, int K_TOTAL, int N_REAL>
__global__ void __launch_bounds__(256) mma_gemm_kernel(
    const float* __restrict__ A, const float* __restrict__ B,
    const float* __restrict__ rowscale, float* __restrict__ C, int M)
{
    constexpr int NPH   = K_TOTAL / 64;
    constexpr int BSTR  = N_TILE + 8;      // B smem row stride (words)
    constexpr int N_W   = N_TILE / 2;      // warp n extent
    constexpr int NT    = N_W / 8;         // n tiles per warp (8 or 4)
    constexpr int A_WORDS = 128 * 68;

    extern __shared__ float smf[];
    float* As = smf;                        // [128][68]
    float* Bs = smf + A_WORDS;              // [64][BSTR]

    int tid = threadIdx.x;
    int wid = tid >> 5;
    int lane = tid & 31;
    int g = lane >> 2;                      // groupID 0..7
    int t = lane & 3;                       // thread-in-group 0..3
    int warp_m = wid >> 1;                  // 0..3
    int warp_n = wid & 1;                   // 0..1
    int mbase = blockIdx.x * 128;

    float acc[2][NT][4];
#pragma unroll
    for (int i = 0; i < 2; i++)
#pragma unroll
        for (int j = 0; j < NT; j++)
#pragma unroll
            for (int q = 0; q < 4; q++) acc[i][j][q] = 0.f;

    for (int p = 0; p < NPH; p++) {
        __syncthreads();   // protect smem reuse from previous phase's compute

        // ---- A phase: rows mbase..+127, cols p*64..+63, scaled + tf32 ----
#pragma unroll
        for (int i = tid; i < 128 * 16; i += 256) {
            int r = i >> 4, c4 = i & 15;
            int grow = mbase + r;
            float4 v = make_float4(0.f, 0.f, 0.f, 0.f);
            if (grow < M) {
                v = *(const float4*)(A + (size_t)grow * K_TOTAL + p * 64 + c4 * 4);
                float sc = rowscale[grow];
                v.x = to_tf32(v.x * sc); v.y = to_tf32(v.y * sc);
                v.z = to_tf32(v.z * sc); v.w = to_tf32(v.w * sc);
            }
            *(float4*)(As + r * 68 + c4 * 4) = v;
        }

        // ---- B phase: k rows p*64..+63, cols 0..N_TILE-1 (pad cols >= N_REAL with 0) ----
        if (N_REAL == N_TILE) {
#pragma unroll
            for (int i = tid; i < 64 * (N_TILE / 4); i += 256) {
                int r = i / (N_TILE / 4), c4 = i % (N_TILE / 4);
                float4 v = *(const float4*)(B + (size_t)(p * 64 + r) * N_REAL + c4 * 4);
                v.x = to_tf32(v.x); v.y = to_tf32(v.y);
                v.z = to_tf32(v.z); v.w = to_tf32(v.w);
                *(float4*)(Bs + r * BSTR + c4 * 4) = v;
            }
        } else {
#pragma unroll
            for (int i = tid; i < 64 * N_TILE; i += 256) {
                int r = i / N_TILE, n = i % N_TILE;
                float v = (n < N_REAL) ? to_tf32(B[(size_t)(p * 64 + r) * N_REAL + n]) : 0.f;
                Bs[r * BSTR + n] = v;
            }
        }
        __syncthreads();

        // ---- compute: 8 k-steps of 8 ----
#pragma unroll
        for (int ks = 0; ks < 8; ks++) {
            int k0 = ks * 8;
            uint32_t af[2][4];
#pragma unroll
            for (int mt = 0; mt < 2; mt++) {
                int rb = warp_m * 32 + mt * 16;
                const uint32_t* Au = (const uint32_t*)As;
                af[mt][0] = Au[(rb + g) * 68 + k0 + t];
                af[mt][1] = Au[(rb + g + 8) * 68 + k0 + t];
                af[mt][2] = Au[(rb + g) * 68 + k0 + t + 4];
                af[mt][3] = Au[(rb + g + 8) * 68 + k0 + t + 4];
            }
#pragma unroll
            for (int nt = 0; nt < NT; nt++) {
                int col = warp_n * N_W + nt * 8 + g;
                const uint32_t* Bu = (const uint32_t*)Bs;
                uint32_t b0 = Bu[(k0 + t) * BSTR + col];
                uint32_t b1 = Bu[(k0 + t + 4) * BSTR + col];
#pragma unroll
                for (int mt = 0; mt < 2; mt++)
                    mma_tf32(acc[mt][nt], af[mt][0], af[mt][1], af[mt][2], af[mt][3], b0, b1);
            }
        }
    }

    // ---- epilogue: c0/c1 at (row, 2t / 2t+1), c2/c3 at (row+8, ...) ----
#pragma unroll
    for (int mt = 0; mt < 2; mt++) {
#pragma unroll
        for (int half = 0; half < 2; half++) {
            int row = mbase + warp_m * 32 + mt * 16 + g + half * 8;
            if (row >= M) continue;
#pragma unroll
            for (int nt = 0; nt < NT; nt++) {
                int col = warp_n * N_W + nt * 8 + 2 * t;
                float c0 = acc[mt][nt][half * 2 + 0];
                float c1 = acc[mt][nt][half * 2 + 1];
                if (N_REAL == N_TILE) {
                    *(float2*)(C + (size_t)row * N_REAL + col) = make_float2(c0, c1);
                } else {
                    if (col < N_REAL)     C[(size_t)row * N_REAL + col] = c0;
                    if (col + 1 < N_REAL) C[(size_t)row * N_REAL + col + 1] = c1;
                }
            }
        }
    }
}

// ---------------- zero degrees ----------------
__global__ void zero_kernel() {
    int i = blockIdx.x * blockDim.x + threadIdx.x;
    if (i < N_NODES) { g_degs[i] = 0; g_degd[i] = 0; }
}

// ---------------- edge index normalization (int64 vs int32 detect) ----------------
__global__ void conv_idx_kernel(const void* __restrict__ ei) {
    const int* p32 = (const int*)ei;
    bool is64 = true;
#pragma unroll
    for (int i = 0; i < 16; i++) is64 = is64 && (p32[2 * i + 1] == 0);

    long long total = 2LL * N_EDGES;
    long long stride = (long long)gridDim.x * blockDim.x;
    for (long long e = blockIdx.x * (long long)blockDim.x + threadIdx.x; e < total; e += stride) {
        int v;
        if (is64) v = (int)((const long long*)ei)[e];
        else      v = p32[e];
        if (e < N_EDGES) g_src[e] = v;
        else             g_dst[e - N_EDGES] = v;
    }
}

// ---------------- degrees + norms ----------------
__global__ void degree_kernel() {
    int stride = gridDim.x * blockDim.x;
    for (int e = blockIdx.x * blockDim.x + threadIdx.x; e < N_EDGES; e += stride) {
        atomicAdd(&g_degs[g_src[e]], 1);
        atomicAdd(&g_degd[g_dst[e]], 1);
    }
}

__global__ void norm_kernel() {
    int i = blockIdx.x * blockDim.x + threadIdx.x;
    if (i < N_NODES) {
        int ds = g_degs[i]; if (ds < 1) ds = 1;
        int dd = g_degd[i]; if (dd < 1) dd = 1;
        g_nsrc[i] = 1.0f / sqrtf((float)ds);
        g_ndst[i] = 1.0f / sqrtf((float)dd);
        g_degs[i] = 0;                       // reuse as CSR fill cursor
    }
    if (i == 0) g_row_ptr[N_NODES] = N_EDGES;
}

// ---------------- 3-step exclusive scan of g_degd -> g_row_ptr ----------------
__global__ void scan1_kernel() {
    __shared__ int sh[256];
    int i = blockIdx.x * 256 + threadIdx.x;
    int v = (i < N_NODES) ? g_degd[i] : 0;
    sh[threadIdx.x] = v;
    __syncthreads();
    for (int o = 128; o > 0; o >>= 1) {
        if (threadIdx.x < o) sh[threadIdx.x] += sh[threadIdx.x + o];
        __syncthreads();
    }
    if (threadIdx.x == 0) g_blocksum[blockIdx.x] = sh[0];
}

__global__ void scan2_kernel() {
    __shared__ int buf[2][512];
    int t = threadIdx.x;
    int v = (t < SCAN_BLOCKS) ? g_blocksum[t] : 0;
    buf[0][t] = v;
    __syncthreads();
    int cur = 0;
#pragma unroll
    for (int o = 1; o < 512; o <<= 1) {
        int nxt = cur ^ 1;
        int val = buf[cur][t];
        if (t >= o) val += buf[cur][t - o];
        buf[nxt][t] = val;
        cur = nxt;
        __syncthreads();
    }
    if (t < SCAN_BLOCKS) g_blockoff[t] = buf[cur][t] - v;  // exclusive
}

__global__ void scan3_kernel() {
    __shared__ int buf[2][256];
    int t = threadIdx.x;
    int i = blockIdx.x * 256 + t;
    int v = (i < N_NODES) ? g_degd[i] : 0;
    buf[0][t] = v;
    __syncthreads();
    int cur = 0;
#pragma unroll
    for (int o = 1; o < 256; o <<= 1) {
        int nxt = cur ^ 1;
        int val = buf[cur][t];
        if (t >= o) val += buf[cur][t - o];
        buf[nxt][t] = val;
        cur = nxt;
        __syncthreads();
    }
    if (i < N_NODES) g_row_ptr[i] = g_blockoff[blockIdx.x] + buf[cur][t] - v;
}

// ---------------- CSR fill: group edges by dst ----------------
__global__ void csr_fill_kernel() {
    int stride = gridDim.x * blockDim.x;
    for (int e = blockIdx.x * blockDim.x + threadIdx.x; e < N_EDGES; e += stride) {
        int d = g_dst[e];
        int pos = g_row_ptr[d] + atomicAdd(&g_degs[d], 1);
        g_csr_src[pos] = g_src[e];
    }
}

// ---------------- JAX threefry2x32 (key = (0, 42)), partitionable path ----------------
__device__ __forceinline__ unsigned rotl32(unsigned x, int r) {
    return (x << r) | (x >> (32 - r));
}

__device__ __forceinline__ unsigned threefry_bits_k42(unsigned x1) {
    const unsigned k0 = 0u, k1 = 42u;
    const unsigned k2 = k0 ^ k1 ^ 0x1BD11BDAu;
    unsigned ks[3] = {k0, k1, k2};
    const int rotE[4] = {13, 15, 26, 6};
    const int rotO[4] = {17, 29, 16, 24};
    unsigned x0 = 0u;
    x0 += ks[0];
    x1 += ks[1];
#pragma unroll
    for (int i = 0; i < 5; i++) {
        const int* rot = (i & 1) ? rotO : rotE;
#pragma unroll
        for (int j = 0; j < 4; j++) {
            x0 += x1;
            x1 = rotl32(x1, rot[j]);
            x1 ^= x0;
        }
        x0 += ks[(i + 1) % 3];
        x1 += ks[(i + 2) % 3] + (unsigned)(i + 1);
    }
    return x0 ^ x1;
}

// ---------------- gather1 + ndst + bias + relu + dropout (warp per node) ----------------
__global__ void gather1_kernel(const float* __restrict__ b1) {
    int node = (blockIdx.x * blockDim.x + threadIdx.x) >> 5;
    int lane = threadIdx.x & 31;
    if (node >= N_NODES) return;
    int beg = g_row_ptr[node], end = g_row_ptr[node + 1];

    float4 acc = make_float4(0.f, 0.f, 0.f, 0.f);
    int e = beg;
    for (; e + 1 < end; e += 2) {
        int s0 = g_csr_src[e];
        int s1 = g_csr_src[e + 1];
        float4 v0 = ((const float4*)(g_h1 + (size_t)s0 * D_H))[lane];
        float4 v1 = ((const float4*)(g_h1 + (size_t)s1 * D_H))[lane];
        acc.x += v0.x; acc.y += v0.y; acc.z += v0.z; acc.w += v0.w;
        acc.x += v1.x; acc.y += v1.y; acc.z += v1.z; acc.w += v1.w;
    }
    if (e < end) {
        int s0 = g_csr_src[e];
        float4 v0 = ((const float4*)(g_h1 + (size_t)s0 * D_H))[lane];
        acc.x += v0.x; acc.y += v0.y; acc.z += v0.z; acc.w += v0.w;
    }

    float nd = g_ndst[node];
    float4 bb = ((const float4*)b1)[lane];
    float r[4];
    r[0] = fmaxf(acc.x * nd + bb.x, 0.f);
    r[1] = fmaxf(acc.y * nd + bb.y, 0.f);
    r[2] = fmaxf(acc.z * nd + bb.z, 0.f);
    r[3] = fmaxf(acc.w * nd + bb.w, 0.f);

    unsigned jbase = ((unsigned)node << 7) + (unsigned)(lane * 4);
#pragma unroll
    for (int t = 0; t < 4; t++) {
        unsigned bits = threefry_bits_k42(jbase + t);
        float u = __uint_as_float((bits >> 9) | 0x3f800000u) - 1.0f;
        r[t] = (u < 0.8f) ? r[t] / 0.8f : 0.f;
    }
    ((float4*)(g_h1d + (size_t)node * D_H))[lane] = make_float4(r[0], r[1], r[2], r[3]);
}

// ---------------- gather2 + ndst + bias + log_softmax (warp per node) ----------------
__global__ void gather2_kernel(const float* __restrict__ b2, float* __restrict__ out) {
    int node = (blockIdx.x * blockDim.x + threadIdx.x) >> 5;
    int lane = threadIdx.x & 31;
    if (node >= N_NODES) return;
    int beg = g_row_ptr[node], end = g_row_ptr[node + 1];
    bool has2 = (lane < D_OUT - 32);   // lane+32 < 47

    float a1 = 0.f, a2 = 0.f;
    for (int e = beg; e < end; e++) {
        int s = g_csr_src[e];
        const float* hs = g_h2 + (size_t)s * D_OUT;
        a1 += hs[lane];
        if (has2) a2 += hs[lane + 32];
    }

    float nd = g_ndst[node];
    float v1 = a1 * nd + b2[lane];
    float v2 = has2 ? (a2 * nd + b2[lane + 32]) : __int_as_float(0xff800000);

    float m = fmaxf(v1, v2);
#pragma unroll
    for (int o = 16; o > 0; o >>= 1) m = fmaxf(m, __shfl_xor_sync(0xffffffffu, m, o));

    float s = expf(v1 - m) + (has2 ? expf(v2 - m) : 0.f);
#pragma unroll
    for (int o = 16; o > 0; o >>= 1) s += __shfl_xor_sync(0xffffffffu, s, o);

    float lse = m + logf(s);
    out[(size_t)node * D_OUT + lane] = v1 - lse;
    if (has2) out[(size_t)node * D_OUT + lane + 32] = v2 - lse;
}

// ---------------- launch ----------------
extern "C" void kernel_launch(void* const* d_in, const int* in_sizes, int n_in,
                              void* d_out, int out_size) {
    const float* x  = (const float*)d_in[0];
    const void*  ei = d_in[1];
    const float* W1 = (const float*)d_in[2];
    const float* b1 = (const float*)d_in[3];
    const float* W2 = (const float*)d_in[4];
    const float* b2 = (const float*)d_in[5];
    float* out = (float*)d_out;

    float *p_h1, *p_h1d, *p_h2, *p_nsrc;
    cudaGetSymbolAddress((void**)&p_h1,   g_h1);
    cudaGetSymbolAddress((void**)&p_h1d,  g_h1d);
    cudaGetSymbolAddress((void**)&p_h2,   g_h2);
    cudaGetSymbolAddress((void**)&p_nsrc, g_nsrc);

    const int SMEM1 = (128 * 68 + 64 * 136) * 4;   // 69632
    const int SMEM2 = (128 * 68 + 64 * 72) * 4;    // 53248
    cudaFuncSetAttribute(mma_gemm_kernel<128, 256, 128>,
                         cudaFuncAttributeMaxDynamicSharedMemorySize, SMEM1);
    cudaFuncSetAttribute(mma_gemm_kernel<64, 128, 47>,
                         cudaFuncAttributeMaxDynamicSharedMemorySize, SMEM2);

    zero_kernel<<<SCAN_BLOCKS, 256>>>();
    conv_idx_kernel<<<12500, 256>>>(ei);
    degree_kernel<<<6250, 256>>>();
    norm_kernel<<<SCAN_BLOCKS, 256>>>();

    scan1_kernel<<<SCAN_BLOCKS, 256>>>();
    scan2_kernel<<<1, 512>>>();
    scan3_kernel<<<SCAN_BLOCKS, 256>>>();
    csr_fill_kernel<<<6250, 256>>>();

    int nblk = (N_NODES + 127) / 128;   // 782

    // h1 = (diag(nsrc)*x) @ W1   via mma.sync tf32
    mma_gemm_kernel<128, 256, 128><<<nblk, 256, SMEM1>>>(x, W1, p_nsrc, p_h1, N_NODES);

    // agg1 + relu + dropout fused (warp per node)
    gather1_kernel<<<(N_NODES * 32 + 255) / 256, 256>>>(b1);

    // h2 = (diag(nsrc)*h1d) @ W2   via mma.sync tf32
    mma_gemm_kernel<64, 128, 47><<<nblk, 256, SMEM2>>>(p_h1d, W2, p_nsrc, p_h2, N_NODES);

    // agg2 + log_softmax fused (warp per node)
    gather2_kernel<<<(N_NODES * 32 + 255) / 256, 256>>>(b2, out);
}